// round 2
// baseline (speedup 1.0000x reference)
#include <cuda_runtime.h>
#include <cstdint>

// ---------------------------------------------------------------------------
// cosFormer linear attention, fp32 SIMT baseline.
// Stages:
//   1. proj:  Q = relu(query @ Wq^T + bq)   (B,L,E)   [same for K; V no relu]
//   2. kv:    KV[b,d,m] = sum_s k_[b,s,d] * v[b,s,m]  (B,2E,E), sin/cos halves
//   3. ksum:  Ksum_{sin,cos}[b,f] = sum_s K[b,s,f]*trig(s)
//   4. z:     Z[b,l] = 1/max(sum_d q_[b,l,d]*ksum_[b,d], eps)
//   5. attn:  out[l,b,m] = Z[b,l] * sum_d q_[b,l,d]*KV[b,d,m]
// ---------------------------------------------------------------------------

#define L_DIM 2048
#define S_DIM 2048
#define B_DIM 4
#define E_DIM 1024
#define D2    (2 * E_DIM)
#define EPS_F 1e-6f
#define PIO2  1.5707963267948966f
#define INV_M (1.0f / 2048.0f)

#define NCHUNK 16  // ksum partial chunks over S

// Scratch (device globals: allocation-free rule)
__device__ float g_Q[(size_t)B_DIM * L_DIM * E_DIM];   // 32 MB
__device__ float g_K[(size_t)B_DIM * S_DIM * E_DIM];   // 32 MB
__device__ float g_V[(size_t)B_DIM * S_DIM * E_DIM];   // 32 MB
__device__ float g_KV[(size_t)B_DIM * D2 * E_DIM];     // 32 MB
__device__ float g_KsumPartS[NCHUNK * B_DIM * E_DIM];
__device__ float g_KsumPartC[NCHUNK * B_DIM * E_DIM];
__device__ float g_KsumS[B_DIM * E_DIM];
__device__ float g_KsumC[B_DIM * E_DIM];
__device__ float g_Z[B_DIM * L_DIM];

// ---------------------------------------------------------------------------
// Stage 1: projection GEMM.  C[m,n] = sum_k X[m,k] * W[n,k] + bias[n]
// X: (M=8192, K=1024) row-major (query/key/value flattened (T,B,E))
// W: (N=1024, K=1024) row-major. Output scattered to (b, t, n) layout.
// 128x128 tile, BK=16, 256 threads, 8x8 per thread.
// ---------------------------------------------------------------------------
__global__ __launch_bounds__(256, 2)
void proj_kernel(const float* __restrict__ X, const float* __restrict__ W,
                 const float* __restrict__ bias, float* __restrict__ out,
                 int do_relu)
{
    __shared__ float As[16][132];
    __shared__ float Bs[16][132];

    const int tid = threadIdx.x;
    const int m0 = blockIdx.y * 128;
    const int n0 = blockIdx.x * 128;
    const int tx = tid & 15;       // 0..15
    const int ty = tid >> 4;       // 0..15
    const int lr = tid >> 2;       // 0..63
    const int lc = tid & 3;        // 0..3

    float acc[8][8];
#pragma unroll
    for (int i = 0; i < 8; i++)
#pragma unroll
        for (int j = 0; j < 8; j++) acc[i][j] = 0.f;

    for (int k0 = 0; k0 < E_DIM; k0 += 16) {
#pragma unroll
        for (int it = 0; it < 2; it++) {
            int row = lr + it * 64;
            float4 a = *(const float4*)&X[(size_t)(m0 + row) * E_DIM + k0 + lc * 4];
            As[lc * 4 + 0][row] = a.x; As[lc * 4 + 1][row] = a.y;
            As[lc * 4 + 2][row] = a.z; As[lc * 4 + 3][row] = a.w;
            float4 w = *(const float4*)&W[(size_t)(n0 + row) * E_DIM + k0 + lc * 4];
            Bs[lc * 4 + 0][row] = w.x; Bs[lc * 4 + 1][row] = w.y;
            Bs[lc * 4 + 2][row] = w.z; Bs[lc * 4 + 3][row] = w.w;
        }
        __syncthreads();
#pragma unroll
        for (int kk = 0; kk < 16; kk++) {
            float a[8], b[8];
#pragma unroll
            for (int i = 0; i < 8; i++) a[i] = As[kk][ty * 8 + i];
#pragma unroll
            for (int j = 0; j < 8; j++) b[j] = Bs[kk][tx * 8 + j];
#pragma unroll
            for (int i = 0; i < 8; i++)
#pragma unroll
                for (int j = 0; j < 8; j++) acc[i][j] += a[i] * b[j];
        }
        __syncthreads();
    }

    // Epilogue: bias (+relu), scatter m=(t*B+b) -> out[b][t][n]
#pragma unroll
    for (int i = 0; i < 8; i++) {
        int m = m0 + ty * 8 + i;
        int b = m & (B_DIM - 1);
        int t = m >> 2;
        float* orow = &out[((size_t)b * L_DIM + t) * E_DIM + n0 + tx * 8];
#pragma unroll
        for (int j = 0; j < 8; j++) {
            float c = acc[i][j] + bias[n0 + tx * 8 + j];
            if (do_relu) c = fmaxf(c, 0.f);
            acc[i][j] = c;
        }
        *(float4*)&orow[0] = make_float4(acc[i][0], acc[i][1], acc[i][2], acc[i][3]);
        *(float4*)&orow[4] = make_float4(acc[i][4], acc[i][5], acc[i][6], acc[i][7]);
    }
}

// ---------------------------------------------------------------------------
// Stage 2: KV state.  KV[b,d,m] = sum_s K[b,s,dmod]*trig(s) * V[b,s,m]
// TN GEMM per batch: d tile 128 (sin half if d0<E else cos), m tile 128.
// ---------------------------------------------------------------------------
__global__ __launch_bounds__(256, 2)
void kv_kernel(const float* __restrict__ Kb, const float* __restrict__ Vb,
               float* __restrict__ KV)
{
    __shared__ float As[16][132];
    __shared__ float Bs[16][132];

    const int b  = blockIdx.z;
    const int d0 = blockIdx.y * 128;
    const int m0 = blockIdx.x * 128;
    const int tid = threadIdx.x;
    const int tx = tid & 15, ty = tid >> 4;

    const bool is_sin = (d0 < E_DIM);
    const int dbase = is_sin ? d0 : (d0 - E_DIM);
    const float* Kp = Kb + (size_t)b * S_DIM * E_DIM;
    const float* Vp = Vb + (size_t)b * S_DIM * E_DIM;

    float acc[8][8];
#pragma unroll
    for (int i = 0; i < 8; i++)
#pragma unroll
        for (int j = 0; j < 8; j++) acc[i][j] = 0.f;

    for (int s0 = 0; s0 < S_DIM; s0 += 16) {
#pragma unroll
        for (int it = 0; it < 2; it++) {
            int id = tid + it * 256;
            int sr = id >> 5;        // 0..15
            int c4 = id & 31;        // 0..31
            int s = s0 + sr;
            float th = PIO2 * (float)(s + 1) * INV_M;
            float w = is_sin ? __sinf(th) : __cosf(th);
            float4 k4 = *(const float4*)&Kp[(size_t)s * E_DIM + dbase + c4 * 4];
            *(float4*)&As[sr][c4 * 4] =
                make_float4(k4.x * w, k4.y * w, k4.z * w, k4.w * w);
            float4 v4 = *(const float4*)&Vp[(size_t)s * E_DIM + m0 + c4 * 4];
            *(float4*)&Bs[sr][c4 * 4] = v4;
        }
        __syncthreads();
#pragma unroll
        for (int kk = 0; kk < 16; kk++) {
            float a[8], bb[8];
#pragma unroll
            for (int i = 0; i < 8; i++) a[i] = As[kk][ty * 8 + i];
#pragma unroll
            for (int j = 0; j < 8; j++) bb[j] = Bs[kk][tx * 8 + j];
#pragma unroll
            for (int i = 0; i < 8; i++)
#pragma unroll
                for (int j = 0; j < 8; j++) acc[i][j] += a[i] * bb[j];
        }
        __syncthreads();
    }

#pragma unroll
    for (int i = 0; i < 8; i++) {
        float* orow = &KV[((size_t)b * D2 + d0 + ty * 8 + i) * E_DIM + m0 + tx * 8];
        *(float4*)&orow[0] = make_float4(acc[i][0], acc[i][1], acc[i][2], acc[i][3]);
        *(float4*)&orow[4] = make_float4(acc[i][4], acc[i][5], acc[i][6], acc[i][7]);
    }
}

// ---------------------------------------------------------------------------
// Stage 3a: ksum partials over S chunks (no atomics).
// ---------------------------------------------------------------------------
__global__ void ksum_part_kernel(const float* __restrict__ Kb)
{
    const int f = blockIdx.x * 256 + threadIdx.x;
    const int b = blockIdx.y;
    const int chunk = blockIdx.z;
    const int s0 = chunk * (S_DIM / NCHUNK);
    const float* Kp = Kb + (size_t)b * S_DIM * E_DIM + f;
    float ss = 0.f, sc = 0.f;
#pragma unroll 4
    for (int i = 0; i < S_DIM / NCHUNK; i++) {
        int s = s0 + i;
        float th = PIO2 * (float)(s + 1) * INV_M;
        float kv = Kp[(size_t)s * E_DIM];
        ss += kv * __sinf(th);
        sc += kv * __cosf(th);
    }
    g_KsumPartS[(chunk * B_DIM + b) * E_DIM + f] = ss;
    g_KsumPartC[(chunk * B_DIM + b) * E_DIM + f] = sc;
}

// Stage 3b: reduce partials
__global__ void ksum_reduce_kernel()
{
    int idx = blockIdx.x * 256 + threadIdx.x;   // idx over B*E
    if (idx >= B_DIM * E_DIM) return;
    float ss = 0.f, sc = 0.f;
#pragma unroll
    for (int c = 0; c < NCHUNK; c++) {
        ss += g_KsumPartS[c * B_DIM * E_DIM + idx];
        sc += g_KsumPartC[c * B_DIM * E_DIM + idx];
    }
    g_KsumS[idx] = ss;
    g_KsumC[idx] = sc;
}

// ---------------------------------------------------------------------------
// Stage 4: normalizer Z[b,l] = 1/max(sum_f Q[b,l,f]*(sl*KsS + cl*KsC), eps)
// ---------------------------------------------------------------------------
__global__ void z_kernel(const float* __restrict__ Qb)
{
    const int l = blockIdx.x;
    const int b = blockIdx.y;
    const int tid = threadIdx.x;
    const float* q = Qb + ((size_t)b * L_DIM + l) * E_DIM;
    const float th = PIO2 * (float)(l + 1) * INV_M;
    const float sl = __sinf(th), cl = __cosf(th);

    float acc = 0.f;
#pragma unroll
    for (int f = tid; f < E_DIM; f += 256)
        acc += q[f] * (sl * g_KsumS[b * E_DIM + f] + cl * g_KsumC[b * E_DIM + f]);

    // block reduction
    __shared__ float red[8];
#pragma unroll
    for (int off = 16; off > 0; off >>= 1)
        acc += __shfl_down_sync(0xFFFFFFFFu, acc, off);
    if ((tid & 31) == 0) red[tid >> 5] = acc;
    __syncthreads();
    if (tid == 0) {
        float s = 0.f;
#pragma unroll
        for (int w = 0; w < 8; w++) s += red[w];
        g_Z[b * L_DIM + l] = 1.f / fmaxf(s, EPS_F);
    }
}

// ---------------------------------------------------------------------------
// Stage 5: output GEMM. out[l,b,m] = Z[b,l] * sum_d q_[b,l,d] * KV[b,d,m]
// NN GEMM per batch: A (L x 2E) generated from Q + trig(l), B = KV (2E x E).
// ---------------------------------------------------------------------------
__global__ __launch_bounds__(256, 2)
void attn_kernel(const float* __restrict__ Qb, const float* __restrict__ KV,
                 float* __restrict__ out)
{
    __shared__ float As[16][132];
    __shared__ float Bs[16][132];

    const int b  = blockIdx.z;
    const int l0 = blockIdx.y * 128;
    const int m0 = blockIdx.x * 128;
    const int tid = threadIdx.x;
    const int tx = tid & 15, ty = tid >> 4;
    const int lr = tid >> 2, lc = tid & 3;

    const float* Qp = Qb + (size_t)b * L_DIM * E_DIM;
    const float* KVp = KV + (size_t)b * D2 * E_DIM;

    float acc[8][8];
#pragma unroll
    for (int i = 0; i < 8; i++)
#pragma unroll
        for (int j = 0; j < 8; j++) acc[i][j] = 0.f;

    for (int d0 = 0; d0 < D2; d0 += 16) {
        const bool is_sin = (d0 < E_DIM);
        const int dbase = is_sin ? d0 : (d0 - E_DIM);
#pragma unroll
        for (int it = 0; it < 2; it++) {
            int row = lr + it * 64;
            int l = l0 + row;
            float th = PIO2 * (float)(l + 1) * INV_M;
            float w = is_sin ? __sinf(th) : __cosf(th);
            float4 q4 = *(const float4*)&Qp[(size_t)l * E_DIM + dbase + lc * 4];
            As[lc * 4 + 0][row] = q4.x * w; As[lc * 4 + 1][row] = q4.y * w;
            As[lc * 4 + 2][row] = q4.z * w; As[lc * 4 + 3][row] = q4.w * w;
            // B: rows d0..d0+15 of KV, cols m0..m0+127 (two rows per thread set)
            int id = tid + it * 256;
            int dr = id >> 5, c4 = id & 31;
            float4 kv4 = *(const float4*)&KVp[(size_t)(d0 + dr) * E_DIM + m0 + c4 * 4];
            *(float4*)&Bs[dr][c4 * 4] = kv4;
        }
        __syncthreads();
#pragma unroll
        for (int kk = 0; kk < 16; kk++) {
            float a[8], bb[8];
#pragma unroll
            for (int i = 0; i < 8; i++) a[i] = As[kk][ty * 8 + i];
#pragma unroll
            for (int j = 0; j < 8; j++) bb[j] = Bs[kk][tx * 8 + j];
#pragma unroll
            for (int i = 0; i < 8; i++)
#pragma unroll
                for (int j = 0; j < 8; j++) acc[i][j] += a[i] * bb[j];
        }
        __syncthreads();
    }

#pragma unroll
    for (int i = 0; i < 8; i++) {
        int l = l0 + ty * 8 + i;
        float zv = g_Z[b * L_DIM + l];
        float* orow = &out[((size_t)l * B_DIM + b) * E_DIM + m0 + tx * 8];
        *(float4*)&orow[0] = make_float4(acc[i][0] * zv, acc[i][1] * zv,
                                         acc[i][2] * zv, acc[i][3] * zv);
        *(float4*)&orow[4] = make_float4(acc[i][4] * zv, acc[i][5] * zv,
                                         acc[i][6] * zv, acc[i][7] * zv);
    }
}

// ---------------------------------------------------------------------------
// Launch
// ---------------------------------------------------------------------------
extern "C" void kernel_launch(void* const* d_in, const int* in_sizes, int n_in,
                              void* d_out, int out_size)
{
    const float* query = (const float*)d_in[0];
    const float* key   = (const float*)d_in[1];
    const float* value = (const float*)d_in[2];
    const float* Wq    = (const float*)d_in[3];
    const float* bq    = (const float*)d_in[4];
    const float* Wk    = (const float*)d_in[5];
    const float* bk    = (const float*)d_in[6];
    const float* Wv    = (const float*)d_in[7];
    const float* bv    = (const float*)d_in[8];
    float* out = (float*)d_out;

    float *Qb, *Kb, *Vb, *KVb;
    cudaGetSymbolAddress((void**)&Qb, g_Q);
    cudaGetSymbolAddress((void**)&Kb, g_K);
    cudaGetSymbolAddress((void**)&Vb, g_V);
    cudaGetSymbolAddress((void**)&KVb, g_KV);

    dim3 gProj(E_DIM / 128, (L_DIM * B_DIM) / 128);   // (8, 64)
    proj_kernel<<<gProj, 256>>>(query, Wq, bq, Qb, 1);
    proj_kernel<<<gProj, 256>>>(key,   Wk, bk, Kb, 1);
    proj_kernel<<<gProj, 256>>>(value, Wv, bv, Vb, 0);

    dim3 gKV(E_DIM / 128, D2 / 128, B_DIM);           // (8, 16, 4)
    kv_kernel<<<gKV, 256>>>(Kb, Vb, KVb);

    dim3 gKsum(E_DIM / 256, B_DIM, NCHUNK);
    ksum_part_kernel<<<gKsum, 256>>>(Kb);
    ksum_reduce_kernel<<<(B_DIM * E_DIM + 255) / 256, 256>>>();

    dim3 gZ(L_DIM, B_DIM);
    z_kernel<<<gZ, 256>>>(Qb);

    dim3 gAttn(E_DIM / 128, L_DIM / 128, B_DIM);      // (8, 16, 4)
    attn_kernel<<<gAttn, 256>>>(Qb, KVb, out);
}

// round 3
// speedup vs baseline: 2.4091x; 2.4091x over previous
#include <cuda_runtime.h>
#include <cuda_bf16.h>
#include <cstdint>

// ---------------------------------------------------------------------------
// cosFormer linear attention — tensor-core bf16x3 split-precision GEMMs.
//   1. proj:  Q = relu(query @ Wq^T + bq)  (B,L,E)  [K same; V no relu]
//   2. kv:    KV[b,d,m] = sum_s K[b,s,dmod]*trig(s) * V[b,s,m]
//   3. ksum / 4. z : normalizer
//   5. attn:  out[l,b,m] = Z[b,l] * sum_d q_[b,l,d]*KV[b,d,m]
// GEMMs use mma.sync.m16n8k16.bf16 with hi/lo split (hh + hl + lh) for
// fp32-like accuracy (~1e-5).
// ---------------------------------------------------------------------------

#define L_DIM 2048
#define S_DIM 2048
#define B_DIM 4
#define E_DIM 1024
#define D2    (2 * E_DIM)
#define EPS_F 1e-6f
#define PIO2  1.5707963267948966f
#define INV_M (1.0f / 2048.0f)
#define NCHUNK 16

#define BKP 24    // A/B [row][k] row length (16 + 8 pad), keeps 16B alignment
#define BNP 136   // B [k][n] row length (128 + 8 pad), 17*16B -> aligned

// Scratch
__device__ float g_Q[(size_t)B_DIM * L_DIM * E_DIM];
__device__ float g_K[(size_t)B_DIM * S_DIM * E_DIM];
__device__ float g_V[(size_t)B_DIM * S_DIM * E_DIM];
__device__ float g_KV[(size_t)B_DIM * D2 * E_DIM];
__device__ float g_KsumPartS[NCHUNK * B_DIM * E_DIM];
__device__ float g_KsumPartC[NCHUNK * B_DIM * E_DIM];
__device__ float g_KsumS[B_DIM * E_DIM];
__device__ float g_KsumC[B_DIM * E_DIM];
__device__ float g_Z[B_DIM * L_DIM];

// ---------------------------------------------------------------------------
// MMA helpers
// ---------------------------------------------------------------------------
__device__ __forceinline__ uint32_t sptr(const void* p) {
    return (uint32_t)__cvta_generic_to_shared(p);
}
__device__ __forceinline__ void ldm_x4(uint32_t* r, uint32_t addr) {
    asm volatile("ldmatrix.sync.aligned.m8n8.x4.shared.b16 {%0,%1,%2,%3}, [%4];"
                 : "=r"(r[0]), "=r"(r[1]), "=r"(r[2]), "=r"(r[3]) : "r"(addr));
}
__device__ __forceinline__ void ldm_x2(uint32_t* r, uint32_t addr) {
    asm volatile("ldmatrix.sync.aligned.m8n8.x2.shared.b16 {%0,%1}, [%2];"
                 : "=r"(r[0]), "=r"(r[1]) : "r"(addr));
}
__device__ __forceinline__ void ldm_x2t(uint32_t* r, uint32_t addr) {
    asm volatile("ldmatrix.sync.aligned.m8n8.x2.trans.shared.b16 {%0,%1}, [%2];"
                 : "=r"(r[0]), "=r"(r[1]) : "r"(addr));
}
__device__ __forceinline__ void mma16816(float* c, const uint32_t* a, const uint32_t* b) {
    asm volatile(
        "mma.sync.aligned.m16n8k16.row.col.f32.bf16.bf16.f32 "
        "{%0,%1,%2,%3}, {%4,%5,%6,%7}, {%8,%9}, {%0,%1,%2,%3};"
        : "+f"(c[0]), "+f"(c[1]), "+f"(c[2]), "+f"(c[3])
        : "r"(a[0]), "r"(a[1]), "r"(a[2]), "r"(a[3]), "r"(b[0]), "r"(b[1]));
}
__device__ __forceinline__ void split_bf16(float x, __nv_bfloat16& h, __nv_bfloat16& l) {
    h = __float2bfloat16(x);
    l = __float2bfloat16(x - __bfloat162float(h));
}

// ---------------------------------------------------------------------------
// Stage 1: projection. C[m,n] = X[m,:]·W[n,:] + bias[n]; scatter to (b,t,n).
// ---------------------------------------------------------------------------
__global__ __launch_bounds__(256)
void proj_mma(const float* __restrict__ X, const float* __restrict__ W,
              const float* __restrict__ bias, float* __restrict__ out,
              int do_relu)
{
    __shared__ __nv_bfloat16 Ah[128][BKP], Al[128][BKP];
    __shared__ __nv_bfloat16 Bh[128][BKP], Bl[128][BKP];

    const int tid = threadIdx.x;
    const int lane = tid & 31, warp = tid >> 5;
    const int wy = warp >> 2, wx = warp & 3;          // 2 x 4 warp grid
    const int m0 = blockIdx.y * 128, n0 = blockIdx.x * 128;
    const int gid = lane >> 2, tig = lane & 3;
    const int lr = tid >> 2, lc = tid & 3;            // loader: rows lr/lr+64, k=lc*4

    // preload k0 = 0
    float4 xa[2], wb[2];
#pragma unroll
    for (int it = 0; it < 2; it++) {
        xa[it] = *(const float4*)&X[(size_t)(m0 + lr + it * 64) * E_DIM + lc * 4];
        wb[it] = *(const float4*)&W[(size_t)(n0 + lr + it * 64) * E_DIM + lc * 4];
    }

    float cacc[4][4][4];
#pragma unroll
    for (int i = 0; i < 4; i++)
#pragma unroll
        for (int j = 0; j < 4; j++)
#pragma unroll
            for (int k = 0; k < 4; k++) cacc[i][j][k] = 0.f;

    uint32_t a_addr[4], b_addr[4];
    {
        int arow = wy * 64 + (lane & 15);
        int acol = (lane >> 4) * 8;
#pragma unroll
        for (int mi = 0; mi < 4; mi++) a_addr[mi] = sptr(&Ah[arow + mi * 16][acol]);
        int brow = wx * 32 + (lane & 7);
        int bcol = ((lane >> 3) & 1) * 8;
#pragma unroll
        for (int ni = 0; ni < 4; ni++) b_addr[ni] = sptr(&Bh[brow + ni * 8][bcol]);
    }
    const uint32_t dA = sptr(&Al[0][0]) - sptr(&Ah[0][0]);
    const uint32_t dB = sptr(&Bl[0][0]) - sptr(&Bh[0][0]);

    for (int k0 = 0; k0 < E_DIM; k0 += 16) {
        // store current tile (split hi/lo)
#pragma unroll
        for (int it = 0; it < 2; it++) {
            int row = lr + it * 64;
            float va[4] = {xa[it].x, xa[it].y, xa[it].z, xa[it].w};
            float vb[4] = {wb[it].x, wb[it].y, wb[it].z, wb[it].w};
            __nv_bfloat16 h[4], l[4], hB[4], lB[4];
#pragma unroll
            for (int j = 0; j < 4; j++) { split_bf16(va[j], h[j], l[j]); split_bf16(vb[j], hB[j], lB[j]); }
            *(__nv_bfloat162*)&Ah[row][lc * 4]     = __halves2bfloat162(h[0], h[1]);
            *(__nv_bfloat162*)&Ah[row][lc * 4 + 2] = __halves2bfloat162(h[2], h[3]);
            *(__nv_bfloat162*)&Al[row][lc * 4]     = __halves2bfloat162(l[0], l[1]);
            *(__nv_bfloat162*)&Al[row][lc * 4 + 2] = __halves2bfloat162(l[2], l[3]);
            *(__nv_bfloat162*)&Bh[row][lc * 4]     = __halves2bfloat162(hB[0], hB[1]);
            *(__nv_bfloat162*)&Bh[row][lc * 4 + 2] = __halves2bfloat162(hB[2], hB[3]);
            *(__nv_bfloat162*)&Bl[row][lc * 4]     = __halves2bfloat162(lB[0], lB[1]);
            *(__nv_bfloat162*)&Bl[row][lc * 4 + 2] = __halves2bfloat162(lB[2], lB[3]);
        }
        __syncthreads();
        if (k0 + 16 < E_DIM) {
#pragma unroll
            for (int it = 0; it < 2; it++) {
                xa[it] = *(const float4*)&X[(size_t)(m0 + lr + it * 64) * E_DIM + k0 + 16 + lc * 4];
                wb[it] = *(const float4*)&W[(size_t)(n0 + lr + it * 64) * E_DIM + k0 + 16 + lc * 4];
            }
        }
        uint32_t ah[4][4], al[4][4], bh[4][2], bl[4][2];
#pragma unroll
        for (int mi = 0; mi < 4; mi++) { ldm_x4(ah[mi], a_addr[mi]); ldm_x4(al[mi], a_addr[mi] + dA); }
#pragma unroll
        for (int ni = 0; ni < 4; ni++) { ldm_x2(bh[ni], b_addr[ni]); ldm_x2(bl[ni], b_addr[ni] + dB); }
#pragma unroll
        for (int mi = 0; mi < 4; mi++)
#pragma unroll
            for (int ni = 0; ni < 4; ni++) mma16816(cacc[mi][ni], ah[mi], bh[ni]);
#pragma unroll
        for (int mi = 0; mi < 4; mi++)
#pragma unroll
            for (int ni = 0; ni < 4; ni++) mma16816(cacc[mi][ni], ah[mi], bl[ni]);
#pragma unroll
        for (int mi = 0; mi < 4; mi++)
#pragma unroll
            for (int ni = 0; ni < 4; ni++) mma16816(cacc[mi][ni], al[mi], bh[ni]);
        __syncthreads();
    }

    // epilogue: bias (+relu), scatter m=(t*B+b) -> out[b][t][n]
#pragma unroll
    for (int ni = 0; ni < 4; ni++) {
        int col = n0 + wx * 32 + ni * 8 + tig * 2;
        float b0v = bias[col], b1v = bias[col + 1];
#pragma unroll
        for (int mi = 0; mi < 4; mi++) {
#pragma unroll
            for (int half = 0; half < 2; half++) {
                int m = m0 + wy * 64 + mi * 16 + gid + half * 8;
                int b = m & (B_DIM - 1);
                int t = m >> 2;
                float v0 = cacc[mi][ni][half * 2 + 0] + b0v;
                float v1 = cacc[mi][ni][half * 2 + 1] + b1v;
                if (do_relu) { v0 = fmaxf(v0, 0.f); v1 = fmaxf(v1, 0.f); }
                *(float2*)&out[((size_t)b * L_DIM + t) * E_DIM + col] = make_float2(v0, v1);
            }
        }
    }
}

// ---------------------------------------------------------------------------
// Stage 2: KV[b,d,m] = sum_s K[b,s,dmod]*trig(s) * V[b,s,m]
// A = K^T (transposed in smem, trig-scaled), B = V ([s][m] smem, ldmatrix.trans)
// ---------------------------------------------------------------------------
__global__ __launch_bounds__(256)
void kv_mma(const float* __restrict__ Kb, const float* __restrict__ Vb,
            float* __restrict__ KV)
{
    __shared__ __nv_bfloat16 Ah[128][BKP], Al[128][BKP];
    __shared__ __nv_bfloat16 Bh[16][BNP], Bl[16][BNP];

    const int tid = threadIdx.x;
    const int lane = tid & 31, warp = tid >> 5;
    const int wy = warp >> 2, wx = warp & 3;
    const int b  = blockIdx.z;
    const int d0 = blockIdx.y * 128, m0 = blockIdx.x * 128;
    const int gid = lane >> 2, tig = lane & 3;

    const bool is_sin = (d0 < E_DIM);
    const int dbase = is_sin ? d0 : (d0 - E_DIM);
    const float* Kp = Kb + (size_t)b * S_DIM * E_DIM;
    const float* Vp = Vb + (size_t)b * S_DIM * E_DIM;

    // A loader: id = tid + it*256; sr = id&15 (s), c4 = id>>4 (d chunk)
    // B loader: id = tid + it*256; vs = id>>5 (s), vc = id&31 (m chunk)
    float4 ka[2], va[2];
#pragma unroll
    for (int it = 0; it < 2; it++) {
        int id = tid + it * 256;
        int sr = id & 15, c4 = id >> 4;
        ka[it] = *(const float4*)&Kp[(size_t)sr * E_DIM + dbase + c4 * 4];
        int vs = id >> 5, vc = id & 31;
        va[it] = *(const float4*)&Vp[(size_t)vs * E_DIM + m0 + vc * 4];
    }

    float cacc[4][4][4];
#pragma unroll
    for (int i = 0; i < 4; i++)
#pragma unroll
        for (int j = 0; j < 4; j++)
#pragma unroll
            for (int k = 0; k < 4; k++) cacc[i][j][k] = 0.f;

    uint32_t a_addr[4], b_addr[4];
    {
        int arow = wy * 64 + (lane & 15);
        int acol = (lane >> 4) * 8;
#pragma unroll
        for (int mi = 0; mi < 4; mi++) a_addr[mi] = sptr(&Ah[arow + mi * 16][acol]);
        int brow = lane & 15;
#pragma unroll
        for (int ni = 0; ni < 4; ni++) b_addr[ni] = sptr(&Bh[brow][wx * 32 + ni * 8]);
    }
    const uint32_t dA = sptr(&Al[0][0]) - sptr(&Ah[0][0]);
    const uint32_t dB = sptr(&Bl[0][0]) - sptr(&Bh[0][0]);

    for (int s0 = 0; s0 < S_DIM; s0 += 16) {
#pragma unroll
        for (int it = 0; it < 2; it++) {
            int id = tid + it * 256;
            int sr = id & 15, c4 = id >> 4;
            float th = PIO2 * (float)(s0 + sr + 1) * INV_M;
            float w = is_sin ? __sinf(th) : __cosf(th);
            float v[4] = {ka[it].x * w, ka[it].y * w, ka[it].z * w, ka[it].w * w};
#pragma unroll
            for (int j = 0; j < 4; j++) {
                __nv_bfloat16 h, l;
                split_bf16(v[j], h, l);
                Ah[c4 * 4 + j][sr] = h;
                Al[c4 * 4 + j][sr] = l;
            }
            int vs = id >> 5, vc = id & 31;
            float vv[4] = {va[it].x, va[it].y, va[it].z, va[it].w};
            __nv_bfloat16 h[4], l[4];
#pragma unroll
            for (int j = 0; j < 4; j++) split_bf16(vv[j], h[j], l[j]);
            *(__nv_bfloat162*)&Bh[vs][vc * 4]     = __halves2bfloat162(h[0], h[1]);
            *(__nv_bfloat162*)&Bh[vs][vc * 4 + 2] = __halves2bfloat162(h[2], h[3]);
            *(__nv_bfloat162*)&Bl[vs][vc * 4]     = __halves2bfloat162(l[0], l[1]);
            *(__nv_bfloat162*)&Bl[vs][vc * 4 + 2] = __halves2bfloat162(l[2], l[3]);
        }
        __syncthreads();
        if (s0 + 16 < S_DIM) {
#pragma unroll
            for (int it = 0; it < 2; it++) {
                int id = tid + it * 256;
                int sr = id & 15, c4 = id >> 4;
                ka[it] = *(const float4*)&Kp[(size_t)(s0 + 16 + sr) * E_DIM + dbase + c4 * 4];
                int vs = id >> 5, vc = id & 31;
                va[it] = *(const float4*)&Vp[(size_t)(s0 + 16 + vs) * E_DIM + m0 + vc * 4];
            }
        }
        uint32_t ah[4][4], al[4][4], bh[4][2], bl[4][2];
#pragma unroll
        for (int mi = 0; mi < 4; mi++) { ldm_x4(ah[mi], a_addr[mi]); ldm_x4(al[mi], a_addr[mi] + dA); }
#pragma unroll
        for (int ni = 0; ni < 4; ni++) { ldm_x2t(bh[ni], b_addr[ni]); ldm_x2t(bl[ni], b_addr[ni] + dB); }
#pragma unroll
        for (int mi = 0; mi < 4; mi++)
#pragma unroll
            for (int ni = 0; ni < 4; ni++) mma16816(cacc[mi][ni], ah[mi], bh[ni]);
#pragma unroll
        for (int mi = 0; mi < 4; mi++)
#pragma unroll
            for (int ni = 0; ni < 4; ni++) mma16816(cacc[mi][ni], ah[mi], bl[ni]);
#pragma unroll
        for (int mi = 0; mi < 4; mi++)
#pragma unroll
            for (int ni = 0; ni < 4; ni++) mma16816(cacc[mi][ni], al[mi], bh[ni]);
        __syncthreads();
    }

#pragma unroll
    for (int mi = 0; mi < 4; mi++)
#pragma unroll
        for (int ni = 0; ni < 4; ni++) {
            int col = m0 + wx * 32 + ni * 8 + tig * 2;
#pragma unroll
            for (int half = 0; half < 2; half++) {
                int d = d0 + wy * 64 + mi * 16 + gid + half * 8;
                *(float2*)&KV[((size_t)b * D2 + d) * E_DIM + col] =
                    make_float2(cacc[mi][ni][half * 2], cacc[mi][ni][half * 2 + 1]);
            }
        }
}

// ---------------------------------------------------------------------------
// Stage 5: out[l,b,m] = Z[b,l] * sum_d q_[b,l,d] * KV[b,d,m]
// ---------------------------------------------------------------------------
__global__ __launch_bounds__(256)
void attn_mma(const float* __restrict__ Qb, const float* __restrict__ KV,
              float* __restrict__ out)
{
    __shared__ __nv_bfloat16 Ah[128][BKP], Al[128][BKP];
    __shared__ __nv_bfloat16 Bh[16][BNP], Bl[16][BNP];

    const int tid = threadIdx.x;
    const int lane = tid & 31, warp = tid >> 5;
    const int wy = warp >> 2, wx = warp & 3;
    const int b  = blockIdx.z;
    const int l0 = blockIdx.y * 128, m0 = blockIdx.x * 128;
    const int gid = lane >> 2, tig = lane & 3;
    const int lr = tid >> 2, lc = tid & 3;

    const float* Qp = Qb + (size_t)b * L_DIM * E_DIM;
    const float* KVp = KV + (size_t)b * D2 * E_DIM;

    // per-thread row trig (fixed rows lr, lr+64)
    float sl[2], cl[2];
#pragma unroll
    for (int it = 0; it < 2; it++) {
        float th = PIO2 * (float)(l0 + lr + it * 64 + 1) * INV_M;
        sl[it] = __sinf(th);
        cl[it] = __cosf(th);
    }

    float4 qa[2], kv4[2];
#pragma unroll
    for (int it = 0; it < 2; it++) {
        qa[it] = *(const float4*)&Qp[(size_t)(l0 + lr + it * 64) * E_DIM + lc * 4];
        int id = tid + it * 256;
        int vs = id >> 5, vc = id & 31;
        kv4[it] = *(const float4*)&KVp[(size_t)vs * E_DIM + m0 + vc * 4];
    }

    float cacc[4][4][4];
#pragma unroll
    for (int i = 0; i < 4; i++)
#pragma unroll
        for (int j = 0; j < 4; j++)
#pragma unroll
            for (int k = 0; k < 4; k++) cacc[i][j][k] = 0.f;

    uint32_t a_addr[4], b_addr[4];
    {
        int arow = wy * 64 + (lane & 15);
        int acol = (lane >> 4) * 8;
#pragma unroll
        for (int mi = 0; mi < 4; mi++) a_addr[mi] = sptr(&Ah[arow + mi * 16][acol]);
        int brow = lane & 15;
#pragma unroll
        for (int ni = 0; ni < 4; ni++) b_addr[ni] = sptr(&Bh[brow][wx * 32 + ni * 8]);
    }
    const uint32_t dA = sptr(&Al[0][0]) - sptr(&Ah[0][0]);
    const uint32_t dB = sptr(&Bl[0][0]) - sptr(&Bh[0][0]);

    for (int d0 = 0; d0 < D2; d0 += 16) {
        const bool is_sin = (d0 < E_DIM);
#pragma unroll
        for (int it = 0; it < 2; it++) {
            int row = lr + it * 64;
            float w = is_sin ? sl[it] : cl[it];
            float v[4] = {qa[it].x * w, qa[it].y * w, qa[it].z * w, qa[it].w * w};
            __nv_bfloat16 h[4], l[4];
#pragma unroll
            for (int j = 0; j < 4; j++) split_bf16(v[j], h[j], l[j]);
            *(__nv_bfloat162*)&Ah[row][lc * 4]     = __halves2bfloat162(h[0], h[1]);
            *(__nv_bfloat162*)&Ah[row][lc * 4 + 2] = __halves2bfloat162(h[2], h[3]);
            *(__nv_bfloat162*)&Al[row][lc * 4]     = __halves2bfloat162(l[0], l[1]);
            *(__nv_bfloat162*)&Al[row][lc * 4 + 2] = __halves2bfloat162(l[2], l[3]);
            int id = tid + it * 256;
            int vs = id >> 5, vc = id & 31;
            float vv[4] = {kv4[it].x, kv4[it].y, kv4[it].z, kv4[it].w};
            __nv_bfloat16 hB[4], lB[4];
#pragma unroll
            for (int j = 0; j < 4; j++) split_bf16(vv[j], hB[j], lB[j]);
            *(__nv_bfloat162*)&Bh[vs][vc * 4]     = __halves2bfloat162(hB[0], hB[1]);
            *(__nv_bfloat162*)&Bh[vs][vc * 4 + 2] = __halves2bfloat162(hB[2], hB[3]);
            *(__nv_bfloat162*)&Bl[vs][vc * 4]     = __halves2bfloat162(lB[0], lB[1]);
            *(__nv_bfloat162*)&Bl[vs][vc * 4 + 2] = __halves2bfloat162(lB[2], lB[3]);
        }
        __syncthreads();
        if (d0 + 16 < D2) {
            int dn = d0 + 16;
            int dbn = (dn < E_DIM) ? dn : (dn - E_DIM);
#pragma unroll
            for (int it = 0; it < 2; it++) {
                qa[it] = *(const float4*)&Qp[(size_t)(l0 + lr + it * 64) * E_DIM + dbn + lc * 4];
                int id = tid + it * 256;
                int vs = id >> 5, vc = id & 31;
                kv4[it] = *(const float4*)&KVp[(size_t)(dn + vs) * E_DIM + m0 + vc * 4];
            }
        }
        uint32_t ah[4][4], al[4][4], bh[4][2], bl[4][2];
#pragma unroll
        for (int mi = 0; mi < 4; mi++) { ldm_x4(ah[mi], a_addr[mi]); ldm_x4(al[mi], a_addr[mi] + dA); }
#pragma unroll
        for (int ni = 0; ni < 4; ni++) { ldm_x2t(bh[ni], b_addr[ni]); ldm_x2t(bl[ni], b_addr[ni] + dB); }
#pragma unroll
        for (int mi = 0; mi < 4; mi++)
#pragma unroll
            for (int ni = 0; ni < 4; ni++) mma16816(cacc[mi][ni], ah[mi], bh[ni]);
#pragma unroll
        for (int mi = 0; mi < 4; mi++)
#pragma unroll
            for (int ni = 0; ni < 4; ni++) mma16816(cacc[mi][ni], ah[mi], bl[ni]);
#pragma unroll
        for (int mi = 0; mi < 4; mi++)
#pragma unroll
            for (int ni = 0; ni < 4; ni++) mma16816(cacc[mi][ni], al[mi], bh[ni]);
        __syncthreads();
    }

#pragma unroll
    for (int mi = 0; mi < 4; mi++)
#pragma unroll
        for (int ni = 0; ni < 4; ni++) {
            int col = m0 + wx * 32 + ni * 8 + tig * 2;
#pragma unroll
            for (int half = 0; half < 2; half++) {
                int l = l0 + wy * 64 + mi * 16 + gid + half * 8;
                float zv = g_Z[b * L_DIM + l];
                *(float2*)&out[((size_t)l * B_DIM + b) * E_DIM + col] =
                    make_float2(cacc[mi][ni][half * 2] * zv, cacc[mi][ni][half * 2 + 1] * zv);
            }
        }
}

// ---------------------------------------------------------------------------
// Stage 3a/3b/4: ksum + normalizer (unchanged fp32)
// ---------------------------------------------------------------------------
__global__ void ksum_part_kernel(const float* __restrict__ Kb)
{
    const int f = blockIdx.x * 256 + threadIdx.x;
    const int b = blockIdx.y;
    const int chunk = blockIdx.z;
    const int s0 = chunk * (S_DIM / NCHUNK);
    const float* Kp = Kb + (size_t)b * S_DIM * E_DIM + f;
    float ss = 0.f, sc = 0.f;
#pragma unroll 4
    for (int i = 0; i < S_DIM / NCHUNK; i++) {
        int s = s0 + i;
        float th = PIO2 * (float)(s + 1) * INV_M;
        float kv = Kp[(size_t)s * E_DIM];
        ss += kv * __sinf(th);
        sc += kv * __cosf(th);
    }
    g_KsumPartS[(chunk * B_DIM + b) * E_DIM + f] = ss;
    g_KsumPartC[(chunk * B_DIM + b) * E_DIM + f] = sc;
}

__global__ void ksum_reduce_kernel()
{
    int idx = blockIdx.x * 256 + threadIdx.x;
    if (idx >= B_DIM * E_DIM) return;
    float ss = 0.f, sc = 0.f;
#pragma unroll
    for (int c = 0; c < NCHUNK; c++) {
        ss += g_KsumPartS[c * B_DIM * E_DIM + idx];
        sc += g_KsumPartC[c * B_DIM * E_DIM + idx];
    }
    g_KsumS[idx] = ss;
    g_KsumC[idx] = sc;
}

__global__ void z_kernel(const float* __restrict__ Qb)
{
    const int l = blockIdx.x;
    const int b = blockIdx.y;
    const int tid = threadIdx.x;
    const float* q = Qb + ((size_t)b * L_DIM + l) * E_DIM;
    const float th = PIO2 * (float)(l + 1) * INV_M;
    const float sl = __sinf(th), cl = __cosf(th);

    float acc = 0.f;
#pragma unroll
    for (int f = tid; f < E_DIM; f += 256)
        acc += q[f] * (sl * g_KsumS[b * E_DIM + f] + cl * g_KsumC[b * E_DIM + f]);

    __shared__ float red[8];
#pragma unroll
    for (int off = 16; off > 0; off >>= 1)
        acc += __shfl_down_sync(0xFFFFFFFFu, acc, off);
    if ((tid & 31) == 0) red[tid >> 5] = acc;
    __syncthreads();
    if (tid == 0) {
        float s = 0.f;
#pragma unroll
        for (int w = 0; w < 8; w++) s += red[w];
        g_Z[b * L_DIM + l] = 1.f / fmaxf(s, EPS_F);
    }
}

// ---------------------------------------------------------------------------
// Launch
// ---------------------------------------------------------------------------
extern "C" void kernel_launch(void* const* d_in, const int* in_sizes, int n_in,
                              void* d_out, int out_size)
{
    const float* query = (const float*)d_in[0];
    const float* key   = (const float*)d_in[1];
    const float* value = (const float*)d_in[2];
    const float* Wq    = (const float*)d_in[3];
    const float* bq    = (const float*)d_in[4];
    const float* Wk    = (const float*)d_in[5];
    const float* bk    = (const float*)d_in[6];
    const float* Wv    = (const float*)d_in[7];
    const float* bv    = (const float*)d_in[8];
    float* out = (float*)d_out;

    float *Qb, *Kb, *Vb, *KVb;
    cudaGetSymbolAddress((void**)&Qb, g_Q);
    cudaGetSymbolAddress((void**)&Kb, g_K);
    cudaGetSymbolAddress((void**)&Vb, g_V);
    cudaGetSymbolAddress((void**)&KVb, g_KV);

    dim3 gProj(E_DIM / 128, (L_DIM * B_DIM) / 128);   // (8, 64)
    proj_mma<<<gProj, 256>>>(query, Wq, bq, Qb, 1);
    proj_mma<<<gProj, 256>>>(key,   Wk, bk, Kb, 1);
    proj_mma<<<gProj, 256>>>(value, Wv, bv, Vb, 0);

    dim3 gKV(E_DIM / 128, D2 / 128, B_DIM);           // (8, 16, 4)
    kv_mma<<<gKV, 256>>>(Kb, Vb, KVb);

    dim3 gKsum(E_DIM / 256, B_DIM, NCHUNK);
    ksum_part_kernel<<<gKsum, 256>>>(Kb);
    ksum_reduce_kernel<<<(B_DIM * E_DIM + 255) / 256, 256>>>();

    dim3 gZ(L_DIM, B_DIM);
    z_kernel<<<gZ, 256>>>(Qb);

    dim3 gAttn(E_DIM / 128, L_DIM / 128, B_DIM);      // (8, 16, 4)
    attn_mma<<<gAttn, 256>>>(Qb, KVb, out);
}